// round 16
// baseline (speedup 1.0000x reference)
#include <cuda_runtime.h>
#include <math.h>
#include <stdint.h>

#define HEADS 8
#define DH    64
#define NQ    4096
#define NK    1024
#define BATCH 2
#define D     512
#define DC    768
#define BH    (BATCH*HEADS)   // 16
#define MQ    (BATCH*NQ)      // 8192
#define MK    (BATCH*NK)      // 2048

// ---------------- scratch (device globals; no allocation allowed) ----------------
__device__ float g_q[MQ*D];
__device__ float g_k[MK*D];
__device__ float g_v[MK*D];
__device__ float g_p[(size_t)BH*NQ*NK];   // exp(sim) fp32 (no max shift; range-safe), 256MB
__device__ int   g_q8 [BH*NQ*16];         // [bh][n][w]  w packs dims 4w..4w+3
__device__ int   g_k8t[BH*16*NK];         // [bh][w][j]
__device__ int   g_v8t[BH*256*DH];        // [bh][w=j/4][d]
__device__ float g_rowz[BH*NQ];
__device__ int   g_maxbits[4];            // 0:q 1:k 2:v 3:attn(max pmax/Z)

// bf16 split buffers (hi = bf16(x), lo = bf16(x - hi))
__device__ uint16_t g_xs_hi[MQ*D],  g_xs_lo[MQ*D];
__device__ uint16_t g_cs_hi[MK*DC], g_cs_lo[MK*DC];
__device__ uint16_t g_wq_hi[D*D],   g_wq_lo[D*D];
__device__ uint16_t g_wk_hi[DC*D],  g_wk_lo[DC*D];
__device__ uint16_t g_wv_hi[DC*D],  g_wv_lo[DC*D];
__device__ uint16_t g_wo_hi[D*D],   g_wo_lo[D*D];
__device__ uint16_t g_oat_hi[MQ*D], g_oat_lo[MQ*D];

__global__ void init_kernel() {
    if (threadIdx.x < 4) g_maxbits[threadIdx.x] = 0;
}

__device__ __forceinline__ uint32_t smem_u32(const void* p) {
    uint32_t a;
    asm("{ .reg .u64 t; cvta.to.shared.u64 t, %1; cvt.u32.u64 %0, t; }" : "=r"(a) : "l"(p));
    return a;
}

// ---------------- mma.sync primitives ----------------
__device__ __forceinline__ void ldsm4(uint32_t* r, uint32_t addr) {
    asm volatile("ldmatrix.sync.aligned.m8n8.x4.shared.b16 {%0,%1,%2,%3}, [%4];"
        : "=r"(r[0]), "=r"(r[1]), "=r"(r[2]), "=r"(r[3]) : "r"(addr));
}
__device__ __forceinline__ void ldsm4t(uint32_t* r, uint32_t addr) {
    asm volatile("ldmatrix.sync.aligned.m8n8.x4.trans.shared.b16 {%0,%1,%2,%3}, [%4];"
        : "=r"(r[0]), "=r"(r[1]), "=r"(r[2]), "=r"(r[3]) : "r"(addr));
}
__device__ __forceinline__ void hmma(float* c, const uint32_t* a, const uint32_t* b) {
    asm volatile(
        "mma.sync.aligned.m16n8k16.row.col.f32.bf16.bf16.f32 "
        "{%0,%1,%2,%3}, {%4,%5,%6,%7}, {%8,%9}, {%0,%1,%2,%3};"
        : "+f"(c[0]), "+f"(c[1]), "+f"(c[2]), "+f"(c[3])
        : "r"(a[0]), "r"(a[1]), "r"(a[2]), "r"(a[3]), "r"(b[0]), "r"(b[1]));
}
__device__ __forceinline__ void split2(float f0, float f1, uint32_t &u1, uint32_t &u2) {
    asm("cvt.rn.bf16x2.f32 %0, %1, %2;" : "=r"(u1) : "f"(f1), "f"(f0));
    float r0 = f0 - __uint_as_float(u1 << 16);
    float r1 = f1 - __uint_as_float(u1 & 0xffff0000u);
    asm("cvt.rn.bf16x2.f32 %0, %1, %2;" : "=r"(u2) : "f"(r1), "f"(r0));
}

// ---------------- cp.async ----------------
__device__ __forceinline__ void cpa16(uint32_t dst, const void* src) {
    asm volatile("cp.async.cg.shared.global [%0], [%1], 16;" :: "r"(dst), "l"(src));
}
#define CP_COMMIT() asm volatile("cp.async.commit_group;" ::: "memory")
#define CP_WAIT1()  asm volatile("cp.async.wait_group 1;" ::: "memory")
#define CP_WAIT0()  asm volatile("cp.async.wait_group 0;" ::: "memory")

// ======== pre-split: fp32 tensors -> bf16 hi/lo global arrays ========
// blocks: x 4096 | ctx 1536 | Wq 256 | Wk 384 | Wv 384 | Wo 256  (6912 total)
__global__ void split_all(const float* __restrict__ x, const float* __restrict__ ctx,
                          const float* __restrict__ Wq, const float* __restrict__ Wk,
                          const float* __restrict__ Wv, const float* __restrict__ Wo) {
    int bid = blockIdx.x;
    const float* src;
    uint16_t *hi, *lo;
    int base;
    if (bid < 4096)      { src = x;   hi = g_xs_hi; lo = g_xs_lo; base = bid; }
    else if (bid < 5632) { src = ctx; hi = g_cs_hi; lo = g_cs_lo; base = bid - 4096; }
    else if (bid < 5888) { src = Wq;  hi = g_wq_hi; lo = g_wq_lo; base = bid - 5632; }
    else if (bid < 6272) { src = Wk;  hi = g_wk_hi; lo = g_wk_lo; base = bid - 5888; }
    else if (bid < 6656) { src = Wv;  hi = g_wv_hi; lo = g_wv_lo; base = bid - 6272; }
    else                 { src = Wo;  hi = g_wo_hi; lo = g_wo_lo; base = bid - 6656; }
    size_t off = ((size_t)base * 256 + threadIdx.x) * 4;
    float4 v = *(const float4*)(src + off);
    uint32_t h0, l0, h1, l1;
    split2(v.x, v.y, h0, l0);
    split2(v.z, v.w, h1, l1);
    *(uint2*)(hi + off) = make_uint2(h0, h1);
    *(uint2*)(lo + off) = make_uint2(l0, l1);
}

// ================= bf16 split-GEMM with cp.async pipeline + multi-job dispatch =================
#define ASPLIT 10240                    // 128 * 80
#define BSPLIT 8704                     // 32 * 272
#define GB_BUF (2*ASPLIT + 2*BSPLIT)    // 37888
#define GB_SMEM (2*GB_BUF)              // 75776

struct GemmJob {
    const uint16_t *Ahi, *Alo, *Bhi, *Blo;
    const float* bias;
    float* C;
    int M, N, K, slot;
};
struct GemmJobs { GemmJob j[3]; };

__global__ __launch_bounds__(256) void gemm_cp(GemmJobs jobs) {
    extern __shared__ __align__(128) char smem[];
    __shared__ float red[8];
    const GemmJob J = jobs.j[blockIdx.z];
    if (blockIdx.y * 128 >= J.M) return;

    const int tid  = threadIdx.x;
    const int lane = tid & 31;
    const int warp = tid >> 5;
    const int row0 = blockIdx.y * 128;
    const int col0 = blockIdx.x * 128;
    const int N = J.N, K = J.K;
    const uint32_t sb = smem_u32(smem);

    const int ar0 = tid >> 2,         as0 = (tid & 3);
    const int ar1 = (tid + 256) >> 2, as1 = as0;
    const int bk0 = tid >> 4,         bs0 = (tid & 15);
    const int bk1 = (tid + 256) >> 4, bs1 = bs0;

    float acc[2][8][4];
    #pragma unroll
    for (int i = 0; i < 2; i++)
        #pragma unroll
        for (int j = 0; j < 8; j++)
            #pragma unroll
            for (int t = 0; t < 4; t++) acc[i][j][t] = 0.0f;

    const uint32_t aLane = (uint32_t)((lane & 15) * 80 + (lane >> 4) * 16 + (warp & 3) * 2560);
    const uint32_t bLane = (uint32_t)((lane & 15) * 272 + (lane >> 4) * 16 + (warp >> 2) * 128 + 2 * ASPLIT);

    auto issue = [&](int buf, int kc) {
        const uint32_t base = sb + buf * GB_BUF;
        cpa16(base + ar0 * 80 + as0 * 16,           J.Ahi + (size_t)(row0 + ar0) * K + kc + as0 * 8);
        cpa16(base + ar1 * 80 + as1 * 16,           J.Ahi + (size_t)(row0 + ar1) * K + kc + as1 * 8);
        cpa16(base + ASPLIT + ar0 * 80 + as0 * 16,  J.Alo + (size_t)(row0 + ar0) * K + kc + as0 * 8);
        cpa16(base + ASPLIT + ar1 * 80 + as1 * 16,  J.Alo + (size_t)(row0 + ar1) * K + kc + as1 * 8);
        const uint32_t bb = base + 2 * ASPLIT;
        cpa16(bb + bk0 * 272 + bs0 * 16,            J.Bhi + (size_t)(kc + bk0) * N + col0 + bs0 * 8);
        cpa16(bb + bk1 * 272 + bs1 * 16,            J.Bhi + (size_t)(kc + bk1) * N + col0 + bs1 * 8);
        cpa16(bb + BSPLIT + bk0 * 272 + bs0 * 16,   J.Blo + (size_t)(kc + bk0) * N + col0 + bs0 * 8);
        cpa16(bb + BSPLIT + bk1 * 272 + bs1 * 16,   J.Blo + (size_t)(kc + bk1) * N + col0 + bs1 * 8);
        CP_COMMIT();
    };

    issue(0, 0);
    int buf = 0;
    for (int kc = 0; kc < K; kc += 32) {
        const bool has = (kc + 32) < K;
        if (has) issue(buf ^ 1, kc + 32);
        if (has) CP_WAIT1(); else CP_WAIT0();
        __syncthreads();

        const uint32_t abase = sb + buf * GB_BUF + aLane;
        const uint32_t bbase = sb + buf * GB_BUF + bLane;
        #pragma unroll
        for (int k16 = 0; k16 < 2; k16++) {
            uint32_t af[2][2][4];
            #pragma unroll
            for (int s = 0; s < 2; s++)
                #pragma unroll
                for (int i = 0; i < 2; i++)
                    ldsm4(af[s][i], abase + s * ASPLIT + i * 1280 + k16 * 32);
            uint32_t bfr[2][4][4];
            #pragma unroll
            for (int t = 0; t < 2; t++)
                #pragma unroll
                for (int nt = 0; nt < 4; nt++)
                    ldsm4t(bfr[t][nt], bbase + t * BSPLIT + k16 * 4352 + nt * 32);
            #pragma unroll
            for (int p = 0; p < 3; p++) {
                const int sa  = (p == 2) ? 1 : 0;
                const int sbl = (p == 1) ? 1 : 0;
                #pragma unroll
                for (int i = 0; i < 2; i++)
                    #pragma unroll
                    for (int j = 0; j < 8; j++)
                        hmma(acc[i][j], af[sa][i], &bfr[sbl][j >> 1][(j & 1) * 2]);
            }
        }
        __syncthreads();
        buf ^= 1;
    }

    const int rowbase = row0 + (warp & 3) * 32;
    const int colbase = col0 + (warp >> 2) * 64;
    float amax = 0.0f;
    #pragma unroll
    for (int i = 0; i < 2; i++) {
        const int r = rowbase + i * 16 + (lane >> 2);
        #pragma unroll
        for (int j = 0; j < 8; j++) {
            const int c = colbase + j * 8 + 2 * (lane & 3);
            float2 v0 = make_float2(acc[i][j][0], acc[i][j][1]);
            float2 v1 = make_float2(acc[i][j][2], acc[i][j][3]);
            if (J.bias) {
                float2 bv = *(const float2*)(J.bias + c);
                v0.x += bv.x; v0.y += bv.y;
                v1.x += bv.x; v1.y += bv.y;
            }
            amax = fmaxf(amax, fmaxf(fmaxf(fabsf(v0.x), fabsf(v0.y)),
                                     fmaxf(fabsf(v1.x), fabsf(v1.y))));
            *(float2*)(J.C + (size_t)r * N + c)       = v0;
            *(float2*)(J.C + (size_t)(r + 8) * N + c) = v1;
        }
    }
    if (J.slot >= 0) {
        #pragma unroll
        for (int o = 16; o; o >>= 1)
            amax = fmaxf(amax, __shfl_xor_sync(0xffffffffu, amax, o));
        if (lane == 0) red[warp] = amax;
        __syncthreads();
        if (tid == 0) {
            float mm = red[0];
            #pragma unroll
            for (int i = 1; i < 8; i++) mm = fmaxf(mm, red[i]);
            atomicMax(&g_maxbits[J.slot], __float_as_int(mm));
        }
    }
}

// ---------------- quantization (merged) ----------------
__device__ __forceinline__ int quant1(float v, float invd) {
    int q = __float2int_rn(v * invd);
    q = max(-128, min(127, q));
    return q & 0xff;
}
__device__ __forceinline__ int pack4(float a, float b, float c, float d, float invd) {
    return quant1(a, invd) | (quant1(b, invd) << 8) |
           (quant1(c, invd) << 16) | (quant1(d, invd) << 24);
}

// blocks: q 4096 | kT 1024 | vT 1024
__global__ void quant_all() {
    int bid = blockIdx.x;
    if (bid < 4096) {
        int tid = bid * 256 + threadIdx.x;
        int dw = tid & 15;
        int n  = (tid >> 4) & (NQ - 1);
        int bh = tid >> 16;
        int b = bh >> 3, h = bh & 7;
        float invd = 127.0f / __int_as_float(g_maxbits[0]);
        float4 v = *(const float4*)(g_q + ((size_t)(b * NQ + n) * D + h * DH + dw * 4));
        g_q8[tid] = pack4(v.x, v.y, v.z, v.w, invd);
    } else if (bid < 5120) {
        int tid = (bid - 4096) * 256 + threadIdx.x;
        int j  = tid & (NK - 1);
        int w  = (tid >> 10) & 15;
        int bh = tid >> 14;
        int b = bh >> 3, h = bh & 7;
        float invd = 127.0f / __int_as_float(g_maxbits[1]);
        float4 v = *(const float4*)(g_k + ((size_t)(b * NK + j) * D + h * DH + w * 4));
        g_k8t[tid] = pack4(v.x, v.y, v.z, v.w, invd);
    } else {
        int tid = (bid - 5120) * 256 + threadIdx.x;
        int d  = tid & 63;
        int w  = (tid >> 6) & 255;
        int bh = tid >> 14;
        int b = bh >> 3, h = bh & 7;
        float invd = 127.0f / __int_as_float(g_maxbits[2]);
        int j0 = w * 4;
        float v0 = g_v[(size_t)(b * NK + j0 + 0) * D + h * DH + d];
        float v1 = g_v[(size_t)(b * NK + j0 + 1) * D + h * DH + d];
        float v2 = g_v[(size_t)(b * NK + j0 + 2) * D + h * DH + d];
        float v3 = g_v[(size_t)(b * NK + j0 + 3) * D + h * DH + d];
        g_v8t[tid] = pack4(v0, v1, v2, v3, invd);
    }
}

// ---------------- int8 mma.sync m16n8k32 ----------------
__device__ __forceinline__ void imma(int* c, int a0, int a1, int a2, int a3,
                                     int b0, int b1) {
    asm volatile(
        "mma.sync.aligned.m16n8k32.row.col.s32.s8.s8.s32 "
        "{%0,%1,%2,%3}, {%4,%5,%6,%7}, {%8,%9}, {%0,%1,%2,%3};"
        : "+r"(c[0]), "+r"(c[1]), "+r"(c[2]), "+r"(c[3])
        : "r"(a0), "r"(a1), "r"(a2), "r"(a3), "r"(b0), "r"(b1));
}

// ======== attention pass 1 (IMMA, single sweep): p = exp(alpha*c) fp32, Z, pmax ========
#define K8S_STRIDE 1032
#define P1_SMEM (16 * K8S_STRIDE * 4)

__global__ __launch_bounds__(256) void attn_pass1() {
    extern __shared__ int k8s[];
    __shared__ float s_m[8];
    const int tid  = threadIdx.x;
    const int lane = tid & 31;
    const int warp = tid >> 5;
    const int bh   = blockIdx.y;
    const int Rw   = blockIdx.x * 128 + warp * 16;

    const int4* src = (const int4*)(g_k8t + (size_t)bh * 16 * NK);
    #pragma unroll
    for (int i = 0; i < 16; i++) {
        int idx = i * 256 + tid;
        int w  = idx >> 8;
        int j4 = idx & 255;
        *(int4*)(k8s + w * K8S_STRIDE + j4 * 4) = src[idx];
    }
    __syncthreads();

    const float dq = __int_as_float(g_maxbits[0]) * (1.0f / 127.0f);
    const float dk = __int_as_float(g_maxbits[1]) * (1.0f / 127.0f);
    const float alpha = dq * dk * 0.125f;

    const int r0 = Rw + (lane >> 2);
    const int* q0 = g_q8 + ((size_t)bh * NQ + r0) * 16;
    const int* q1 = q0 + 8 * 16;
    int a[2][4];
    #pragma unroll
    for (int ks = 0; ks < 2; ks++) {
        a[ks][0] = q0[ks * 8 + (lane & 3)];
        a[ks][1] = q1[ks * 8 + (lane & 3)];
        a[ks][2] = q0[ks * 8 + 4 + (lane & 3)];
        a[ks][3] = q1[ks * 8 + 4 + (lane & 3)];
    }

    float* pr0 = g_p + ((size_t)bh * NQ + r0) * NK;
    float* pr1 = pr0 + (size_t)8 * NK;
    float z0 = 0.0f, z1 = 0.0f;
    float pm0 = 0.0f, pm1 = 0.0f;
    for (int jb = 0; jb < 128; jb++) {
        int c[4] = {0, 0, 0, 0};
        #pragma unroll
        for (int ks = 0; ks < 2; ks++) {
            int b0 = k8s[(ks * 8 + (lane & 3)) * K8S_STRIDE + jb * 8 + (lane >> 2)];
            int b1 = k8s[(ks * 8 + 4 + (lane & 3)) * K8S_STRIDE + jb * 8 + (lane >> 2)];
            imma(c, a[ks][0], a[ks][1], a[ks][2], a[ks][3], b0, b1);
        }
        float e00 = __expf((float)c[0] * alpha);
        float e01 = __expf((float)c[1] * alpha);
        float e10 = __expf((float)c[2] * alpha);
        float e11 = __expf((float)c[3] * alpha);
        z0 += e00 + e01;
        z1 += e10 + e11;
        pm0 = fmaxf(pm0, fmaxf(e00, e01));
        pm1 = fmaxf(pm1, fmaxf(e10, e11));
        const int col = jb * 8 + 2 * (lane & 3);
        *(float2*)(pr0 + col) = make_float2(e00, e01);
        *(float2*)(pr1 + col) = make_float2(e10, e11);
    }
    z0 += __shfl_xor_sync(0xffffffffu, z0, 1);
    z0 += __shfl_xor_sync(0xffffffffu, z0, 2);
    z1 += __shfl_xor_sync(0xffffffffu, z1, 1);
    z1 += __shfl_xor_sync(0xffffffffu, z1, 2);
    pm0 = fmaxf(pm0, __shfl_xor_sync(0xffffffffu, pm0, 1));
    pm0 = fmaxf(pm0, __shfl_xor_sync(0xffffffffu, pm0, 2));
    pm1 = fmaxf(pm1, __shfl_xor_sync(0xffffffffu, pm1, 1));
    pm1 = fmaxf(pm1, __shfl_xor_sync(0xffffffffu, pm1, 2));

    if ((lane & 3) == 0) {
        g_rowz[(size_t)bh * NQ + r0]     = z0;
        g_rowz[(size_t)bh * NQ + r0 + 8] = z1;
    }
    float inv = fmaxf(pm0 / z0, pm1 / z1);
    #pragma unroll
    for (int o = 16; o; o >>= 1) inv = fmaxf(inv, __shfl_xor_sync(0xffffffffu, inv, o));
    if (lane == 0) s_m[warp] = inv;
    __syncthreads();
    if (tid == 0) {
        float mm = s_m[0];
        #pragma unroll
        for (int i = 1; i < 8; i++) mm = fmaxf(mm, s_m[i]);
        atomicMax(&g_maxbits[3], __float_as_int(mm));
    }
}

// ======== attention pass 2 (IMMA): quantize stored fp32 p, int8 AV, write oattn splits ========
#define V8S_STRIDE 260
#define AQ_STRIDE  68
#define P2_V_INTS  (64 * V8S_STRIDE)
#define P2_SMEM    ((P2_V_INTS + 8 * 16 * AQ_STRIDE) * 4)

__global__ __launch_bounds__(256) void attn_pass2() {
    extern __shared__ int sm2[];
    int* v8s = sm2;
    int* aqb = sm2 + P2_V_INTS;
    const int tid  = threadIdx.x;
    const int lane = tid & 31;
    const int warp = tid >> 5;
    const int bh   = blockIdx.y;
    const int Rw   = blockIdx.x * 128 + warp * 16;
    const int b = bh >> 3, h = bh & 7;

    const int* vsrc = g_v8t + (size_t)bh * 256 * DH;
    #pragma unroll
    for (int i = 0; i < 64; i++) {
        int idx = i * 256 + tid;
        int w = idx >> 6, d = idx & 63;
        v8s[d * V8S_STRIDE + w] = vsrc[idx];
    }
    __syncthreads();

    const float amax = __int_as_float(g_maxbits[3]);
    const float da   = amax * (1.0f / 127.0f);
    const float dv   = __int_as_float(g_maxbits[2]) * (1.0f / 127.0f);

    const int rloc = lane >> 1;
    const float rz = g_rowz[(size_t)bh * NQ + Rw + rloc];
    const float escale = (127.0f / amax) / rz;
    const float* prow = g_p + ((size_t)bh * NQ + Rw + rloc) * NK + (lane & 1) * 128;

    int acc[8][4];
    #pragma unroll
    for (int i = 0; i < 8; i++)
        #pragma unroll
        for (int j = 0; j < 4; j++) acc[i][j] = 0;

    int* aqw = aqb + warp * 16 * AQ_STRIDE;

    for (int ch = 0; ch < 4; ch++) {
        const float* pp = prow + ch * 256;
        int* dst = aqw + rloc * AQ_STRIDE + (lane & 1) * 32;
        #pragma unroll
        for (int g = 0; g < 32; g++) {
            float4 pv = *(const float4*)(pp + g * 4);
            int a0 = min(127, __float2int_rn(pv.x * escale));
            int a1 = min(127, __float2int_rn(pv.y * escale));
            int a2 = min(127, __float2int_rn(pv.z * escale));
            int a3 = min(127, __float2int_rn(pv.w * escale));
            dst[g] = a0 | (a1 << 8) | (a2 << 16) | (a3 << 24);
        }
        __syncwarp();

        #pragma unroll
        for (int js = 0; js < 8; js++) {
            int a0 = aqw[(lane >> 2) * AQ_STRIDE + js * 8 + (lane & 3)];
            int a1 = aqw[((lane >> 2) + 8) * AQ_STRIDE + js * 8 + (lane & 3)];
            int a2 = aqw[(lane >> 2) * AQ_STRIDE + js * 8 + 4 + (lane & 3)];
            int a3 = aqw[((lane >> 2) + 8) * AQ_STRIDE + js * 8 + 4 + (lane & 3)];
            const int wbase = ch * 64 + js * 8;
            #pragma unroll
            for (int db = 0; db < 8; db++) {
                int b0 = v8s[(db * 8 + (lane >> 2)) * V8S_STRIDE + wbase + (lane & 3)];
                int b1 = v8s[(db * 8 + (lane >> 2)) * V8S_STRIDE + wbase + 4 + (lane & 3)];
                imma(acc[db], a0, a1, a2, a3, b0, b1);
            }
        }
        __syncwarp();
    }

    // epilogue: write bf16 splits of oattn directly (consumed by out-proj gemm)
    const float oscale = da * dv;
    const int r = Rw + (lane >> 2);
    const size_t base0 = ((size_t)(b * NQ) + r) * D + h * DH;
    const size_t base1 = base0 + (size_t)8 * D;
    #pragma unroll
    for (int db = 0; db < 8; db++) {
        const int col = db * 8 + 2 * (lane & 3);
        uint32_t h0, l0, h1, l1;
        split2((float)acc[db][0] * oscale, (float)acc[db][1] * oscale, h0, l0);
        split2((float)acc[db][2] * oscale, (float)acc[db][3] * oscale, h1, l1);
        *(uint32_t*)(g_oat_hi + base0 + col) = h0;
        *(uint32_t*)(g_oat_lo + base0 + col) = l0;
        *(uint32_t*)(g_oat_hi + base1 + col) = h1;
        *(uint32_t*)(g_oat_lo + base1 + col) = l1;
    }
}

// ================= launch =================
extern "C" void kernel_launch(void* const* d_in, const int* in_sizes, int n_in,
                              void* d_out, int out_size) {
    const float* x   = (const float*)d_in[0];
    const float* ctx = (const float*)d_in[1];
    const float* Wq  = (const float*)d_in[2];
    const float* Wk  = (const float*)d_in[3];
    const float* Wv  = (const float*)d_in[4];
    const float* Wo  = (const float*)d_in[5];
    const float* bo  = (const float*)d_in[6];
    float* out = (float*)d_out;

    void *pq, *pk, *pv;
    cudaGetSymbolAddress(&pq, g_q);
    cudaGetSymbolAddress(&pk, g_k);
    cudaGetSymbolAddress(&pv, g_v);
    void *xs_hi, *xs_lo, *cs_hi, *cs_lo, *wq_hi, *wq_lo, *wk_hi, *wk_lo,
         *wv_hi, *wv_lo, *wo_hi, *wo_lo, *oat_hi, *oat_lo;
    cudaGetSymbolAddress(&xs_hi, g_xs_hi);  cudaGetSymbolAddress(&xs_lo, g_xs_lo);
    cudaGetSymbolAddress(&cs_hi, g_cs_hi);  cudaGetSymbolAddress(&cs_lo, g_cs_lo);
    cudaGetSymbolAddress(&wq_hi, g_wq_hi);  cudaGetSymbolAddress(&wq_lo, g_wq_lo);
    cudaGetSymbolAddress(&wk_hi, g_wk_hi);  cudaGetSymbolAddress(&wk_lo, g_wk_lo);
    cudaGetSymbolAddress(&wv_hi, g_wv_hi);  cudaGetSymbolAddress(&wv_lo, g_wv_lo);
    cudaGetSymbolAddress(&wo_hi, g_wo_hi);  cudaGetSymbolAddress(&wo_lo, g_wo_lo);
    cudaGetSymbolAddress(&oat_hi, g_oat_hi); cudaGetSymbolAddress(&oat_lo, g_oat_lo);

    cudaFuncSetAttribute(gemm_cp,    cudaFuncAttributeMaxDynamicSharedMemorySize, GB_SMEM);
    cudaFuncSetAttribute(attn_pass1, cudaFuncAttributeMaxDynamicSharedMemorySize, P1_SMEM);
    cudaFuncSetAttribute(attn_pass2, cudaFuncAttributeMaxDynamicSharedMemorySize, P2_SMEM);

    init_kernel<<<1, 32>>>();
    split_all<<<6912, 256>>>(x, ctx, Wq, Wk, Wv, Wo);

    // q + k + v projections in ONE launch (z-dispatched jobs; empty y-tiles exit)
    GemmJobs qkv;
    qkv.j[0] = { (const uint16_t*)xs_hi, (const uint16_t*)xs_lo,
                 (const uint16_t*)wq_hi, (const uint16_t*)wq_lo,
                 nullptr, (float*)pq, MQ, D, D, 0 };
    qkv.j[1] = { (const uint16_t*)cs_hi, (const uint16_t*)cs_lo,
                 (const uint16_t*)wk_hi, (const uint16_t*)wk_lo,
                 nullptr, (float*)pk, MK, D, DC, 1 };
    qkv.j[2] = { (const uint16_t*)cs_hi, (const uint16_t*)cs_lo,
                 (const uint16_t*)wv_hi, (const uint16_t*)wv_lo,
                 nullptr, (float*)pv, MK, D, DC, 2 };
    gemm_cp<<<dim3(D / 128, MQ / 128, 3), 256, GB_SMEM>>>(qkv);

    quant_all<<<6144, 256>>>();

    attn_pass1<<<dim3(NQ / 128, BH), 256, P1_SMEM>>>();
    attn_pass2<<<dim3(NQ / 128, BH), 256, P2_SMEM>>>();

    // output projection (+bias), reads oattn splits written by pass2
    GemmJobs oj;
    oj.j[0] = { (const uint16_t*)oat_hi, (const uint16_t*)oat_lo,
                (const uint16_t*)wo_hi, (const uint16_t*)wo_lo,
                bo, out, MQ, D, D, -1 };
    oj.j[1] = oj.j[0];
    oj.j[2] = oj.j[0];
    gemm_cp<<<dim3(D / 128, MQ / 128, 1), 256, GB_SMEM>>>(oj);
}

// round 17
// speedup vs baseline: 1.0474x; 1.0474x over previous
#include <cuda_runtime.h>
#include <math.h>
#include <stdint.h>

#define HEADS 8
#define DH    64
#define NQ    4096
#define NK    1024
#define BATCH 2
#define D     512
#define DC    768
#define BH    (BATCH*HEADS)   // 16
#define MQ    (BATCH*NQ)      // 8192
#define MK    (BATCH*NK)      // 2048

// ---------------- scratch (device globals; no allocation allowed) ----------------
__device__ float g_q[MQ*D];
__device__ float g_k[MK*D];
__device__ float g_v[MK*D];
__device__ float g_p[(size_t)BH*NQ*NK];   // exp(sim) fp32 (no max shift; range-safe), 256MB
__device__ int   g_q8 [BH*NQ*16];         // [bh][n][w]  w packs dims 4w..4w+3
__device__ int   g_k8t[BH*16*NK];         // [bh][w][j]
__device__ int   g_v8t[BH*256*DH];        // [bh][w=j/4][d]
__device__ float g_rowz[BH*NQ];
__device__ int   g_maxbits[4];            // 0:q 1:k 2:v 3:attn(max pmax/Z)

// bf16 split buffers (hi = bf16(x), lo = bf16(x - hi))
__device__ uint16_t g_xs_hi[MQ*D],  g_xs_lo[MQ*D];
__device__ uint16_t g_cs_hi[MK*DC], g_cs_lo[MK*DC];
__device__ uint16_t g_wq_hi[D*D],   g_wq_lo[D*D];
__device__ uint16_t g_wk_hi[DC*D],  g_wk_lo[DC*D];
__device__ uint16_t g_wv_hi[DC*D],  g_wv_lo[DC*D];
__device__ uint16_t g_wo_hi[D*D],   g_wo_lo[D*D];
__device__ uint16_t g_oat_hi[MQ*D], g_oat_lo[MQ*D];

__global__ void init_kernel() {
    if (threadIdx.x < 4) g_maxbits[threadIdx.x] = 0;
}

__device__ __forceinline__ uint32_t smem_u32(const void* p) {
    uint32_t a;
    asm("{ .reg .u64 t; cvta.to.shared.u64 t, %1; cvt.u32.u64 %0, t; }" : "=r"(a) : "l"(p));
    return a;
}

// ---------------- mma.sync primitives ----------------
__device__ __forceinline__ void ldsm4(uint32_t* r, uint32_t addr) {
    asm volatile("ldmatrix.sync.aligned.m8n8.x4.shared.b16 {%0,%1,%2,%3}, [%4];"
        : "=r"(r[0]), "=r"(r[1]), "=r"(r[2]), "=r"(r[3]) : "r"(addr));
}
__device__ __forceinline__ void ldsm4t(uint32_t* r, uint32_t addr) {
    asm volatile("ldmatrix.sync.aligned.m8n8.x4.trans.shared.b16 {%0,%1,%2,%3}, [%4];"
        : "=r"(r[0]), "=r"(r[1]), "=r"(r[2]), "=r"(r[3]) : "r"(addr));
}
__device__ __forceinline__ void hmma(float* c, const uint32_t* a, const uint32_t* b) {
    asm volatile(
        "mma.sync.aligned.m16n8k16.row.col.f32.bf16.bf16.f32 "
        "{%0,%1,%2,%3}, {%4,%5,%6,%7}, {%8,%9}, {%0,%1,%2,%3};"
        : "+f"(c[0]), "+f"(c[1]), "+f"(c[2]), "+f"(c[3])
        : "r"(a[0]), "r"(a[1]), "r"(a[2]), "r"(a[3]), "r"(b[0]), "r"(b[1]));
}
__device__ __forceinline__ void split2(float f0, float f1, uint32_t &u1, uint32_t &u2) {
    asm("cvt.rn.bf16x2.f32 %0, %1, %2;" : "=r"(u1) : "f"(f1), "f"(f0));
    float r0 = f0 - __uint_as_float(u1 << 16);
    float r1 = f1 - __uint_as_float(u1 & 0xffff0000u);
    asm("cvt.rn.bf16x2.f32 %0, %1, %2;" : "=r"(u2) : "f"(r1), "f"(r0));
}

// ---------------- cp.async ----------------
__device__ __forceinline__ void cpa16(uint32_t dst, const void* src) {
    asm volatile("cp.async.cg.shared.global [%0], [%1], 16;" :: "r"(dst), "l"(src));
}
#define CP_COMMIT() asm volatile("cp.async.commit_group;" ::: "memory")
#define CP_WAIT1()  asm volatile("cp.async.wait_group 1;" ::: "memory")
#define CP_WAIT0()  asm volatile("cp.async.wait_group 0;" ::: "memory")

// ======== pre-split: fp32 tensors -> bf16 hi/lo global arrays ========
// blocks: x 4096 | ctx 1536 | Wq 256 | Wk 384 | Wv 384 | Wo 256  (6912 total)
__global__ void split_all(const float* __restrict__ x, const float* __restrict__ ctx,
                          const float* __restrict__ Wq, const float* __restrict__ Wk,
                          const float* __restrict__ Wv, const float* __restrict__ Wo) {
    int bid = blockIdx.x;
    const float* src;
    uint16_t *hi, *lo;
    int base;
    if (bid < 4096)      { src = x;   hi = g_xs_hi; lo = g_xs_lo; base = bid; }
    else if (bid < 5632) { src = ctx; hi = g_cs_hi; lo = g_cs_lo; base = bid - 4096; }
    else if (bid < 5888) { src = Wq;  hi = g_wq_hi; lo = g_wq_lo; base = bid - 5632; }
    else if (bid < 6272) { src = Wk;  hi = g_wk_hi; lo = g_wk_lo; base = bid - 5888; }
    else if (bid < 6656) { src = Wv;  hi = g_wv_hi; lo = g_wv_lo; base = bid - 6272; }
    else                 { src = Wo;  hi = g_wo_hi; lo = g_wo_lo; base = bid - 6656; }
    size_t off = ((size_t)base * 256 + threadIdx.x) * 4;
    float4 v = *(const float4*)(src + off);
    uint32_t h0, l0, h1, l1;
    split2(v.x, v.y, h0, l0);
    split2(v.z, v.w, h1, l1);
    *(uint2*)(hi + off) = make_uint2(h0, h1);
    *(uint2*)(lo + off) = make_uint2(l0, l1);
}

// ================= bf16 split-GEMM with cp.async pipeline + multi-job dispatch =================
#define ASPLIT 10240                    // 128 * 80
#define BSPLIT 8704                     // 32 * 272
#define GB_BUF (2*ASPLIT + 2*BSPLIT)    // 37888
#define GB_SMEM (2*GB_BUF)              // 75776

struct GemmJob {
    const uint16_t *Ahi, *Alo, *Bhi, *Blo;
    const float* bias;
    float* C;
    int M, N, K, slot;
};
struct GemmJobs { GemmJob j[3]; };

__global__ __launch_bounds__(256) void gemm_cp(GemmJobs jobs) {
    extern __shared__ __align__(128) char smem[];
    __shared__ float red[8];
    const GemmJob J = jobs.j[blockIdx.z];
    if (blockIdx.y * 128 >= J.M) return;

    const int tid  = threadIdx.x;
    const int lane = tid & 31;
    const int warp = tid >> 5;
    const int row0 = blockIdx.y * 128;
    const int col0 = blockIdx.x * 128;
    const int N = J.N, K = J.K;
    const uint32_t sb = smem_u32(smem);

    const int ar0 = tid >> 2,         as0 = (tid & 3);
    const int ar1 = (tid + 256) >> 2, as1 = as0;
    const int bk0 = tid >> 4,         bs0 = (tid & 15);
    const int bk1 = (tid + 256) >> 4, bs1 = bs0;

    float acc[2][8][4];
    #pragma unroll
    for (int i = 0; i < 2; i++)
        #pragma unroll
        for (int j = 0; j < 8; j++)
            #pragma unroll
            for (int t = 0; t < 4; t++) acc[i][j][t] = 0.0f;

    const uint32_t aLane = (uint32_t)((lane & 15) * 80 + (lane >> 4) * 16 + (warp & 3) * 2560);
    const uint32_t bLane = (uint32_t)((lane & 15) * 272 + (lane >> 4) * 16 + (warp >> 2) * 128 + 2 * ASPLIT);

    auto issue = [&](int buf, int kc) {
        const uint32_t base = sb + buf * GB_BUF;
        cpa16(base + ar0 * 80 + as0 * 16,           J.Ahi + (size_t)(row0 + ar0) * K + kc + as0 * 8);
        cpa16(base + ar1 * 80 + as1 * 16,           J.Ahi + (size_t)(row0 + ar1) * K + kc + as1 * 8);
        cpa16(base + ASPLIT + ar0 * 80 + as0 * 16,  J.Alo + (size_t)(row0 + ar0) * K + kc + as0 * 8);
        cpa16(base + ASPLIT + ar1 * 80 + as1 * 16,  J.Alo + (size_t)(row0 + ar1) * K + kc + as1 * 8);
        const uint32_t bb = base + 2 * ASPLIT;
        cpa16(bb + bk0 * 272 + bs0 * 16,            J.Bhi + (size_t)(kc + bk0) * N + col0 + bs0 * 8);
        cpa16(bb + bk1 * 272 + bs1 * 16,            J.Bhi + (size_t)(kc + bk1) * N + col0 + bs1 * 8);
        cpa16(bb + BSPLIT + bk0 * 272 + bs0 * 16,   J.Blo + (size_t)(kc + bk0) * N + col0 + bs0 * 8);
        cpa16(bb + BSPLIT + bk1 * 272 + bs1 * 16,   J.Blo + (size_t)(kc + bk1) * N + col0 + bs1 * 8);
        CP_COMMIT();
    };

    issue(0, 0);
    int buf = 0;
    for (int kc = 0; kc < K; kc += 32) {
        const bool has = (kc + 32) < K;
        if (has) issue(buf ^ 1, kc + 32);
        if (has) CP_WAIT1(); else CP_WAIT0();
        __syncthreads();

        const uint32_t abase = sb + buf * GB_BUF + aLane;
        const uint32_t bbase = sb + buf * GB_BUF + bLane;
        #pragma unroll
        for (int k16 = 0; k16 < 2; k16++) {
            uint32_t af[2][2][4];
            #pragma unroll
            for (int s = 0; s < 2; s++)
                #pragma unroll
                for (int i = 0; i < 2; i++)
                    ldsm4(af[s][i], abase + s * ASPLIT + i * 1280 + k16 * 32);
            uint32_t bfr[2][4][4];
            #pragma unroll
            for (int t = 0; t < 2; t++)
                #pragma unroll
                for (int nt = 0; nt < 4; nt++)
                    ldsm4t(bfr[t][nt], bbase + t * BSPLIT + k16 * 4352 + nt * 32);
            #pragma unroll
            for (int p = 0; p < 3; p++) {
                const int sa  = (p == 2) ? 1 : 0;
                const int sbl = (p == 1) ? 1 : 0;
                #pragma unroll
                for (int i = 0; i < 2; i++)
                    #pragma unroll
                    for (int j = 0; j < 8; j++)
                        hmma(acc[i][j], af[sa][i], &bfr[sbl][j >> 1][(j & 1) * 2]);
            }
        }
        __syncthreads();
        buf ^= 1;
    }

    const int rowbase = row0 + (warp & 3) * 32;
    const int colbase = col0 + (warp >> 2) * 64;
    float amax = 0.0f;
    #pragma unroll
    for (int i = 0; i < 2; i++) {
        const int r = rowbase + i * 16 + (lane >> 2);
        #pragma unroll
        for (int j = 0; j < 8; j++) {
            const int c = colbase + j * 8 + 2 * (lane & 3);
            float2 v0 = make_float2(acc[i][j][0], acc[i][j][1]);
            float2 v1 = make_float2(acc[i][j][2], acc[i][j][3]);
            if (J.bias) {
                float2 bv = *(const float2*)(J.bias + c);
                v0.x += bv.x; v0.y += bv.y;
                v1.x += bv.x; v1.y += bv.y;
            }
            amax = fmaxf(amax, fmaxf(fmaxf(fabsf(v0.x), fabsf(v0.y)),
                                     fmaxf(fabsf(v1.x), fabsf(v1.y))));
            *(float2*)(J.C + (size_t)r * N + c)       = v0;
            *(float2*)(J.C + (size_t)(r + 8) * N + c) = v1;
        }
    }
    if (J.slot >= 0) {
        #pragma unroll
        for (int o = 16; o; o >>= 1)
            amax = fmaxf(amax, __shfl_xor_sync(0xffffffffu, amax, o));
        if (lane == 0) red[warp] = amax;
        __syncthreads();
        if (tid == 0) {
            float mm = red[0];
            #pragma unroll
            for (int i = 1; i < 8; i++) mm = fmaxf(mm, red[i]);
            atomicMax(&g_maxbits[J.slot], __float_as_int(mm));
        }
    }
}

// ---------------- quantization (merged) ----------------
__device__ __forceinline__ int quant1(float v, float invd) {
    int q = __float2int_rn(v * invd);
    q = max(-128, min(127, q));
    return q & 0xff;
}
__device__ __forceinline__ int pack4(float a, float b, float c, float d, float invd) {
    return quant1(a, invd) | (quant1(b, invd) << 8) |
           (quant1(c, invd) << 16) | (quant1(d, invd) << 24);
}

// blocks: q 4096 | kT 1024 | vT 1024
__global__ void quant_all() {
    int bid = blockIdx.x;
    if (bid < 4096) {
        int tid = bid * 256 + threadIdx.x;
        int dw = tid & 15;
        int n  = (tid >> 4) & (NQ - 1);
        int bh = tid >> 16;
        int b = bh >> 3, h = bh & 7;
        float invd = 127.0f / __int_as_float(g_maxbits[0]);
        float4 v = *(const float4*)(g_q + ((size_t)(b * NQ + n) * D + h * DH + dw * 4));
        g_q8[tid] = pack4(v.x, v.y, v.z, v.w, invd);
    } else if (bid < 5120) {
        int tid = (bid - 4096) * 256 + threadIdx.x;
        int j  = tid & (NK - 1);
        int w  = (tid >> 10) & 15;
        int bh = tid >> 14;
        int b = bh >> 3, h = bh & 7;
        float invd = 127.0f / __int_as_float(g_maxbits[1]);
        float4 v = *(const float4*)(g_k + ((size_t)(b * NK + j) * D + h * DH + w * 4));
        g_k8t[tid] = pack4(v.x, v.y, v.z, v.w, invd);
    } else {
        int tid = (bid - 5120) * 256 + threadIdx.x;
        int d  = tid & 63;
        int w  = (tid >> 6) & 255;
        int bh = tid >> 14;
        int b = bh >> 3, h = bh & 7;
        float invd = 127.0f / __int_as_float(g_maxbits[2]);
        int j0 = w * 4;
        float v0 = g_v[(size_t)(b * NK + j0 + 0) * D + h * DH + d];
        float v1 = g_v[(size_t)(b * NK + j0 + 1) * D + h * DH + d];
        float v2 = g_v[(size_t)(b * NK + j0 + 2) * D + h * DH + d];
        float v3 = g_v[(size_t)(b * NK + j0 + 3) * D + h * DH + d];
        g_v8t[tid] = pack4(v0, v1, v2, v3, invd);
    }
}

// ---------------- int8 mma.sync m16n8k32 ----------------
__device__ __forceinline__ void imma(int* c, int a0, int a1, int a2, int a3,
                                     int b0, int b1) {
    asm volatile(
        "mma.sync.aligned.m16n8k32.row.col.s32.s8.s8.s32 "
        "{%0,%1,%2,%3}, {%4,%5,%6,%7}, {%8,%9}, {%0,%1,%2,%3};"
        : "+r"(c[0]), "+r"(c[1]), "+r"(c[2]), "+r"(c[3])
        : "r"(a0), "r"(a1), "r"(a2), "r"(a3), "r"(b0), "r"(b1));
}

// ======== attention pass 1 (IMMA, single sweep): p = exp(alpha*c) fp32, Z, pmax ========
#define K8S_STRIDE 1032
#define P1_SMEM (16 * K8S_STRIDE * 4)

__global__ __launch_bounds__(256) void attn_pass1() {
    extern __shared__ int k8s[];
    __shared__ float s_m[8];
    const int tid  = threadIdx.x;
    const int lane = tid & 31;
    const int warp = tid >> 5;
    const int bh   = blockIdx.y;
    const int Rw   = blockIdx.x * 128 + warp * 16;

    const int4* src = (const int4*)(g_k8t + (size_t)bh * 16 * NK);
    #pragma unroll
    for (int i = 0; i < 16; i++) {
        int idx = i * 256 + tid;
        int w  = idx >> 8;
        int j4 = idx & 255;
        *(int4*)(k8s + w * K8S_STRIDE + j4 * 4) = src[idx];
    }
    __syncthreads();

    const float dq = __int_as_float(g_maxbits[0]) * (1.0f / 127.0f);
    const float dk = __int_as_float(g_maxbits[1]) * (1.0f / 127.0f);
    const float alpha = dq * dk * 0.125f;

    const int r0 = Rw + (lane >> 2);
    const int* q0 = g_q8 + ((size_t)bh * NQ + r0) * 16;
    const int* q1 = q0 + 8 * 16;
    int a[2][4];
    #pragma unroll
    for (int ks = 0; ks < 2; ks++) {
        a[ks][0] = q0[ks * 8 + (lane & 3)];
        a[ks][1] = q1[ks * 8 + (lane & 3)];
        a[ks][2] = q0[ks * 8 + 4 + (lane & 3)];
        a[ks][3] = q1[ks * 8 + 4 + (lane & 3)];
    }

    float* pr0 = g_p + ((size_t)bh * NQ + r0) * NK;
    float* pr1 = pr0 + (size_t)8 * NK;
    float z0 = 0.0f, z1 = 0.0f;
    float pm0 = 0.0f, pm1 = 0.0f;
    for (int jb = 0; jb < 128; jb++) {
        int c[4] = {0, 0, 0, 0};
        #pragma unroll
        for (int ks = 0; ks < 2; ks++) {
            int b0 = k8s[(ks * 8 + (lane & 3)) * K8S_STRIDE + jb * 8 + (lane >> 2)];
            int b1 = k8s[(ks * 8 + 4 + (lane & 3)) * K8S_STRIDE + jb * 8 + (lane >> 2)];
            imma(c, a[ks][0], a[ks][1], a[ks][2], a[ks][3], b0, b1);
        }
        float e00 = __expf((float)c[0] * alpha);
        float e01 = __expf((float)c[1] * alpha);
        float e10 = __expf((float)c[2] * alpha);
        float e11 = __expf((float)c[3] * alpha);
        z0 += e00 + e01;
        z1 += e10 + e11;
        pm0 = fmaxf(pm0, fmaxf(e00, e01));
        pm1 = fmaxf(pm1, fmaxf(e10, e11));
        const int col = jb * 8 + 2 * (lane & 3);
        *(float2*)(pr0 + col) = make_float2(e00, e01);
        *(float2*)(pr1 + col) = make_float2(e10, e11);
    }
    z0 += __shfl_xor_sync(0xffffffffu, z0, 1);
    z0 += __shfl_xor_sync(0xffffffffu, z0, 2);
    z1 += __shfl_xor_sync(0xffffffffu, z1, 1);
    z1 += __shfl_xor_sync(0xffffffffu, z1, 2);
    pm0 = fmaxf(pm0, __shfl_xor_sync(0xffffffffu, pm0, 1));
    pm0 = fmaxf(pm0, __shfl_xor_sync(0xffffffffu, pm0, 2));
    pm1 = fmaxf(pm1, __shfl_xor_sync(0xffffffffu, pm1, 1));
    pm1 = fmaxf(pm1, __shfl_xor_sync(0xffffffffu, pm1, 2));

    if ((lane & 3) == 0) {
        g_rowz[(size_t)bh * NQ + r0]     = z0;
        g_rowz[(size_t)bh * NQ + r0 + 8] = z1;
    }
    float inv = fmaxf(pm0 / z0, pm1 / z1);
    #pragma unroll
    for (int o = 16; o; o >>= 1) inv = fmaxf(inv, __shfl_xor_sync(0xffffffffu, inv, o));
    if (lane == 0) s_m[warp] = inv;
    __syncthreads();
    if (tid == 0) {
        float mm = s_m[0];
        #pragma unroll
        for (int i = 1; i < 8; i++) mm = fmaxf(mm, s_m[i]);
        atomicMax(&g_maxbits[3], __float_as_int(mm));
    }
}

// ======== attention pass 2 (IMMA): fragment-direct quantize of p, int8 AV ========
// A-fragments quantized straight from coalesced float4 loads of g_p (no AQ smem).
// Tile order reversed vs pass1 so pass2 reads the most-recently-written p first
// (L2 is 126MB; p is 256MB -> large reuse window).
#define V8S_STRIDE 260
#define P2_SMEM (64 * V8S_STRIDE * 4)

__device__ __forceinline__ int pquant(float4 v, float esc) {
    int a0 = min(127, __float2int_rn(v.x * esc));
    int a1 = min(127, __float2int_rn(v.y * esc));
    int a2 = min(127, __float2int_rn(v.z * esc));
    int a3 = min(127, __float2int_rn(v.w * esc));
    return a0 | (a1 << 8) | (a2 << 16) | (a3 << 24);
}

__global__ __launch_bounds__(256) void attn_pass2() {
    extern __shared__ int v8s[];
    const int tid  = threadIdx.x;
    const int lane = tid & 31;
    const int warp = tid >> 5;
    const int bx   = gridDim.x - 1 - blockIdx.x;   // reversed tile order
    const int bh   = gridDim.y - 1 - blockIdx.y;
    const int Rw   = bx * 128 + warp * 16;
    const int b = bh >> 3, h = bh & 7;

    const int* vsrc = g_v8t + (size_t)bh * 256 * DH;
    #pragma unroll
    for (int i = 0; i < 64; i++) {
        int idx = i * 256 + tid;
        int w = idx >> 6, d = idx & 63;
        v8s[d * V8S_STRIDE + w] = vsrc[idx];
    }
    __syncthreads();

    const float amax = __int_as_float(g_maxbits[3]);
    const float da   = amax * (1.0f / 127.0f);
    const float dv   = __int_as_float(g_maxbits[2]) * (1.0f / 127.0f);

    const int r0 = Rw + (lane >> 2);
    const float esc0 = (127.0f / amax) / g_rowz[(size_t)bh * NQ + r0];
    const float esc1 = (127.0f / amax) / g_rowz[(size_t)bh * NQ + r0 + 8];
    const float* p0 = g_p + ((size_t)bh * NQ + r0) * NK;
    const float* p1 = p0 + (size_t)8 * NK;

    int acc[8][4];
    #pragma unroll
    for (int i = 0; i < 8; i++)
        #pragma unroll
        for (int j = 0; j < 4; j++) acc[i][j] = 0;

    #pragma unroll 4
    for (int s = 0; s < 32; s++) {
        const int jo = s * 32 + (lane & 3) * 4;
        float4 x0 = *(const float4*)(p0 + jo);
        float4 x1 = *(const float4*)(p0 + jo + 16);
        float4 y0 = *(const float4*)(p1 + jo);
        float4 y1 = *(const float4*)(p1 + jo + 16);
        const int a0 = pquant(x0, esc0);
        const int a1 = pquant(y0, esc1);
        const int a2 = pquant(x1, esc0);
        const int a3 = pquant(y1, esc1);
        const int wbase = s * 8;
        #pragma unroll
        for (int db = 0; db < 8; db++) {
            int b0 = v8s[(db * 8 + (lane >> 2)) * V8S_STRIDE + wbase + (lane & 3)];
            int b1 = v8s[(db * 8 + (lane >> 2)) * V8S_STRIDE + wbase + 4 + (lane & 3)];
            imma(acc[db], a0, a1, a2, a3, b0, b1);
        }
    }

    // epilogue: write bf16 splits of oattn directly (consumed by out-proj gemm)
    const float oscale = da * dv;
    const int r = Rw + (lane >> 2);
    const size_t base0 = ((size_t)(b * NQ) + r) * D + h * DH;
    const size_t base1 = base0 + (size_t)8 * D;
    #pragma unroll
    for (int db = 0; db < 8; db++) {
        const int col = db * 8 + 2 * (lane & 3);
        uint32_t h0, l0, h1, l1;
        split2((float)acc[db][0] * oscale, (float)acc[db][1] * oscale, h0, l0);
        split2((float)acc[db][2] * oscale, (float)acc[db][3] * oscale, h1, l1);
        *(uint32_t*)(g_oat_hi + base0 + col) = h0;
        *(uint32_t*)(g_oat_lo + base0 + col) = l0;
        *(uint32_t*)(g_oat_hi + base1 + col) = h1;
        *(uint32_t*)(g_oat_lo + base1 + col) = l1;
    }
}

// ================= launch =================
extern "C" void kernel_launch(void* const* d_in, const int* in_sizes, int n_in,
                              void* d_out, int out_size) {
    const float* x   = (const float*)d_in[0];
    const float* ctx = (const float*)d_in[1];
    const float* Wq  = (const float*)d_in[2];
    const float* Wk  = (const float*)d_in[3];
    const float* Wv  = (const float*)d_in[4];
    const float* Wo  = (const float*)d_in[5];
    const float* bo  = (const float*)d_in[6];
    float* out = (float*)d_out;

    void *pq, *pk, *pv;
    cudaGetSymbolAddress(&pq, g_q);
    cudaGetSymbolAddress(&pk, g_k);
    cudaGetSymbolAddress(&pv, g_v);
    void *xs_hi, *xs_lo, *cs_hi, *cs_lo, *wq_hi, *wq_lo, *wk_hi, *wk_lo,
         *wv_hi, *wv_lo, *wo_hi, *wo_lo, *oat_hi, *oat_lo;
    cudaGetSymbolAddress(&xs_hi, g_xs_hi);  cudaGetSymbolAddress(&xs_lo, g_xs_lo);
    cudaGetSymbolAddress(&cs_hi, g_cs_hi);  cudaGetSymbolAddress(&cs_lo, g_cs_lo);
    cudaGetSymbolAddress(&wq_hi, g_wq_hi);  cudaGetSymbolAddress(&wq_lo, g_wq_lo);
    cudaGetSymbolAddress(&wk_hi, g_wk_hi);  cudaGetSymbolAddress(&wk_lo, g_wk_lo);
    cudaGetSymbolAddress(&wv_hi, g_wv_hi);  cudaGetSymbolAddress(&wv_lo, g_wv_lo);
    cudaGetSymbolAddress(&wo_hi, g_wo_hi);  cudaGetSymbolAddress(&wo_lo, g_wo_lo);
    cudaGetSymbolAddress(&oat_hi, g_oat_hi); cudaGetSymbolAddress(&oat_lo, g_oat_lo);

    cudaFuncSetAttribute(gemm_cp,    cudaFuncAttributeMaxDynamicSharedMemorySize, GB_SMEM);
    cudaFuncSetAttribute(attn_pass1, cudaFuncAttributeMaxDynamicSharedMemorySize, P1_SMEM);
    cudaFuncSetAttribute(attn_pass2, cudaFuncAttributeMaxDynamicSharedMemorySize, P2_SMEM);

    init_kernel<<<1, 32>>>();
    split_all<<<6912, 256>>>(x, ctx, Wq, Wk, Wv, Wo);

    // q + k + v projections in ONE launch (z-dispatched jobs; empty y-tiles exit)
    GemmJobs qkv;
    qkv.j[0] = { (const uint16_t*)xs_hi, (const uint16_t*)xs_lo,
                 (const uint16_t*)wq_hi, (const uint16_t*)wq_lo,
                 nullptr, (float*)pq, MQ, D, D, 0 };
    qkv.j[1] = { (const uint16_t*)cs_hi, (const uint16_t*)cs_lo,
                 (const uint16_t*)wk_hi, (const uint16_t*)wk_lo,
                 nullptr, (float*)pk, MK, D, DC, 1 };
    qkv.j[2] = { (const uint16_t*)cs_hi, (const uint16_t*)cs_lo,
                 (const uint16_t*)wv_hi, (const uint16_t*)wv_lo,
                 nullptr, (float*)pv, MK, D, DC, 2 };
    gemm_cp<<<dim3(D / 128, MQ / 128, 3), 256, GB_SMEM>>>(qkv);

    quant_all<<<6144, 256>>>();

    attn_pass1<<<dim3(NQ / 128, BH), 256, P1_SMEM>>>();
    attn_pass2<<<dim3(NQ / 128, BH), 256, P2_SMEM>>>();

    // output projection (+bias), reads oattn splits written by pass2
    GemmJobs oj;
    oj.j[0] = { (const uint16_t*)oat_hi, (const uint16_t*)oat_lo,
                (const uint16_t*)wo_hi, (const uint16_t*)wo_lo,
                bo, out, MQ, D, D, -1 };
    oj.j[1] = oj.j[0];
    oj.j[2] = oj.j[0];
    gemm_cp<<<dim3(D / 128, MQ / 128, 1), 256, GB_SMEM>>>(oj);
}